// round 3
// baseline (speedup 1.0000x reference)
#include <cuda_runtime.h>
#include <cstdint>

typedef unsigned long long ULL;

// Problem constants: B=128, T=1024, H=128, D=64, L=3
#define BB   128
#define TT   1024
#define HH   128
#define G4   512
#define MROWS (BB*TT)

// Scratch (device globals: allocation-rule-safe)
__device__ float g_xg[(size_t)MROWS * G4];   // 256 MB
__device__ float g_y [(size_t)MROWS * HH];   // 64 MB

// ---------------------------------------------------------------------------
// helpers
// ---------------------------------------------------------------------------
__device__ __forceinline__ void fma2(ULL& acc, ULL a, ULL b) {
    asm("fma.rn.f32x2 %0, %1, %2, %0;" : "+l"(acc) : "l"(a), "l"(b));
}
__device__ __forceinline__ ULL pk2(float lo, float hi) {
    ULL r; asm("mov.b64 %0, {%1, %2};" : "=l"(r) : "f"(lo), "f"(hi)); return r;
}
__device__ __forceinline__ void upk2(ULL v, float& lo, float& hi) {
    asm("mov.b64 {%0, %1}, %2;" : "=f"(lo), "=f"(hi) : "l"(v));
}
__device__ __forceinline__ float sigf(float x) {
    return __fdividef(1.f, 1.f + __expf(-x));
}
__device__ __forceinline__ float tanhfast(float x) {
    return 1.f - 2.f * __fdividef(1.f, __expf(2.f * x) + 1.f);
}
__device__ __forceinline__ uint32_t smem_u32(const void* p) {
    uint32_t a;
    asm("{ .reg .u64 t; cvta.to.shared.u64 t, %1; cvt.u32.u64 %0, t; }"
        : "=r"(a) : "l"(p));
    return a;
}
__device__ __forceinline__ uint32_t mapa_u32(uint32_t a, uint32_t rank) {
    uint32_t r;
    asm("mapa.shared::cluster.u32 %0, %1, %2;" : "=r"(r) : "r"(a), "r"(rank));
    return r;
}

// ---------------------------------------------------------------------------
// xg GEMM: g_xg[m, 0:512] = A[m, 0:K] @ W[512, K]^T + (bih + bhh)
// (unchanged from R2 — passed; tensor-core rewrite is a later round)
// ---------------------------------------------------------------------------
template<int K>
__global__ __launch_bounds__(256, 2)
void xg_gemm(const float* __restrict__ Aext, int use_gy,
             const float* __restrict__ W,
             const float* __restrict__ bih,
             const float* __restrict__ bhh)
{
    const int BM = 128, BN = 128, BK = 8;
    __shared__ __align__(16) float As[BK][BM + 4];
    __shared__ __align__(16) float Bs[BK][BN + 4];

    const float* A = use_gy ? (const float*)g_y : Aext;
    float* out = g_xg;

    int tid = threadIdx.x;
    int tx = tid & 15, ty = tid >> 4;
    int m0 = blockIdx.y * BM, n0 = blockIdx.x * BN;

    int am = tid >> 1, ak = (tid & 1) * 4;
    int wn = tid >> 1, wk = (tid & 1) * 4;

    ULL acc[8][4];
#pragma unroll
    for (int i = 0; i < 8; i++)
#pragma unroll
        for (int j = 0; j < 4; j++) acc[i][j] = 0ULL;

    float4 a_ld = *(const float4*)(A + (size_t)(m0 + am) * K + ak);
    float4 b_ld = *(const float4*)(W + (size_t)(n0 + wn) * K + wk);

    const int NC = K / BK;
    for (int c = 0; c < NC; ++c) {
        As[ak + 0][am] = a_ld.x; As[ak + 1][am] = a_ld.y;
        As[ak + 2][am] = a_ld.z; As[ak + 3][am] = a_ld.w;
        Bs[wk + 0][wn] = b_ld.x; Bs[wk + 1][wn] = b_ld.y;
        Bs[wk + 2][wn] = b_ld.z; Bs[wk + 3][wn] = b_ld.w;
        __syncthreads();

        if (c + 1 < NC) {
            a_ld = *(const float4*)(A + (size_t)(m0 + am) * K + (c + 1) * BK + ak);
            b_ld = *(const float4*)(W + (size_t)(n0 + wn) * K + (c + 1) * BK + wk);
        }

#pragma unroll
        for (int k = 0; k < BK; k++) {
            float4 t0 = *(const float4*)&As[k][ty * 8];
            float4 t1 = *(const float4*)&As[k][ty * 8 + 4];
            float av[8] = {t0.x, t0.y, t0.z, t0.w, t1.x, t1.y, t1.z, t1.w};
            const ulonglong2* bbp = (const ulonglong2*)(&Bs[k][tx * 8]);
            ulonglong2 b01 = bbp[0];
            ulonglong2 b23 = bbp[1];
#pragma unroll
            for (int i = 0; i < 8; i++) {
                ULL ai = pk2(av[i], av[i]);
                fma2(acc[i][0], ai, b01.x);
                fma2(acc[i][1], ai, b01.y);
                fma2(acc[i][2], ai, b23.x);
                fma2(acc[i][3], ai, b23.y);
            }
        }
        __syncthreads();
    }

    float bias[8];
#pragma unroll
    for (int j = 0; j < 8; j++) {
        int n = n0 + tx * 8 + j;
        bias[j] = bih[n] + bhh[n];
    }
#pragma unroll
    for (int i = 0; i < 8; i++) {
        size_t row = (size_t)(m0 + ty * 8 + i) * G4 + n0 + tx * 8;
#pragma unroll
        for (int j = 0; j < 4; j++) {
            float lo, hi; upk2(acc[i][j], lo, hi);
            float2 v = make_float2(lo + bias[2 * j], hi + bias[2 * j + 1]);
            *(float2*)(out + row + 2 * j) = v;
        }
    }
}

// ---------------------------------------------------------------------------
// Recurrent scan, cluster of 2 CTAs per 2 batch rows. Rank r owns h-cols
// [r*64, r*64+64). 512 threads: kh = tid>>8 (k-half, warp-group), jp = tid&255
// -> Whh row g*128 + r*64 + nn (g=jp>>6, nn=jp&63), k-half kh: 64 fp32 = 32
// packed regs/thread. GATE threads = first 128 threads of the PEER-k group
// (kh == r^1) so the local-k warps start the next matvec while gate warps'
// sends drain. One release-arrive per gate warp (mbar count=4), not 128.
// ---------------------------------------------------------------------------
__global__ __launch_bounds__(512, 1) __cluster_dims__(2, 1, 1)
void lstm_rec3(const float* __restrict__ whh,
               const float* __restrict__ h0l,
               const float* __restrict__ c0l,
               float* __restrict__ hNl,
               float* __restrict__ cNl)
{
    __shared__ __align__(16) float hbuf[2][2][132];  // [parity][row][n] padded
    __shared__ __align__(8)  float pre[2][512];      // [kh][jp*2 + row]
    __shared__ __align__(8)  ULL   bar;

    const int tid = threadIdx.x;
    const int r   = blockIdx.x & 1;
    const int b0  = (blockIdx.x >> 1) * 2;

    const int kh = tid >> 8;
    const int jp = tid & 255;
    const int g  = jp >> 6;
    const int nn = jp & 63;

    uint32_t bar_addr = smem_u32(&bar);
    uint32_t peer_bar = mapa_u32(bar_addr, (uint32_t)(r ^ 1));

    if (tid == 0) {
        asm volatile("mbarrier.init.shared.b64 [%0], %1;"
                     :: "r"(bar_addr), "r"(4) : "memory");
    }
    // h(-1) = h0 at parity 1 (full vector, loaded locally by both CTAs)
    if (tid < 256) {
        int row = tid >> 7, n = tid & 127;
        hbuf[1][row][n] = h0l[(b0 + row) * HH + n];
    }

    // weights -> registers
    const int row_w = g * 128 + r * 64 + nn;
    ULL w2[32];
    const ULL* wp = (const ULL*)(whh + row_w * HH + kh * 64);
#pragma unroll
    for (int i = 0; i < 32; i++) w2[i] = wp[i];

    // gate role: first 128 threads of the PEER-k warp group
    const bool is_gate = (kh == (r ^ 1)) && (jp < 128);
    const int row_g = jp & 1;
    const int nn_g  = jp >> 1;           // [0,64)
    const int n_g   = r * 64 + nn_g;

    float c = 0.f, hlast = 0.f;
    const float* px = g_xg + ((size_t)(b0 + row_g) * TT) * G4 + n_g;
    float*       py = g_y  + ((size_t)(b0 + row_g) * TT) * HH + n_g;
    uint32_t ph0 = 0, ph1 = 0;
    float xc0=0,xc1=0,xc2=0,xc3=0, xn0=0,xn1=0,xn2=0,xn3=0;
    if (is_gate) {
        c   = c0l[(b0 + row_g) * HH + n_g];
        ph0 = mapa_u32(smem_u32(&hbuf[0][row_g][n_g]), (uint32_t)(r ^ 1));
        ph1 = mapa_u32(smem_u32(&hbuf[1][row_g][n_g]), (uint32_t)(r ^ 1));
        xc0 = px[0];        xc1 = px[128];        xc2 = px[256];        xc3 = px[384];
        xn0 = px[G4 + 0];   xn1 = px[G4 + 128];   xn2 = px[G4 + 256];   xn3 = px[G4 + 384];
    }

    __syncthreads();
    asm volatile("barrier.cluster.arrive.aligned;" ::: "memory");
    asm volatile("barrier.cluster.wait.aligned;"   ::: "memory");

    for (int t = 0; t < TT; ++t) {
        const int pr = (t + 1) & 1;              // parity holding h(t-1)

        if (kh != r && t > 0) {                  // peer-k warps wait for h(t-1)
            unsigned par = (unsigned)((t - 1) & 1);
            asm volatile(
                "{\n\t"
                ".reg .pred P1;\n\t"
                "WLP%=:\n\t"
                "mbarrier.try_wait.parity.acquire.cluster.shared::cta.b64 P1, [%0], %1, 0x989680;\n\t"
                "@!P1 bra WLP%=;\n\t"
                "}"
                :: "r"(bar_addr), "r"(par) : "memory");
        }

        // matvec over this thread's 64-k half, both batch rows
        ULL a00 = 0, a01 = 0, a10 = 0, a11 = 0;
        const ulonglong2* hv0 = (const ulonglong2*)&hbuf[pr][0][kh * 64];
        const ulonglong2* hv1 = (const ulonglong2*)&hbuf[pr][1][kh * 64];
#pragma unroll
        for (int i = 0; i < 16; i++) {
            ulonglong2 u0 = hv0[i], u1 = hv1[i];
            fma2(a00, w2[2 * i],     u0.x);
            fma2(a01, w2[2 * i + 1], u0.y);
            fma2(a10, w2[2 * i],     u1.x);
            fma2(a11, w2[2 * i + 1], u1.y);
        }
        float s0, s1;
        { float x0,x1,x2,x3; upk2(a00,x0,x1); upk2(a01,x2,x3); s0 = (x0+x1)+(x2+x3); }
        { float x0,x1,x2,x3; upk2(a10,x0,x1); upk2(a11,x2,x3); s1 = (x0+x1)+(x2+x3); }
        *(float2*)&pre[kh][jp * 2] = make_float2(s0, s1);
        __syncthreads();

        if (is_gate) {
            float pi = pre[0][(      nn_g) * 2 + row_g] + pre[1][(      nn_g) * 2 + row_g];
            float pf = pre[0][( 64 + nn_g) * 2 + row_g] + pre[1][( 64 + nn_g) * 2 + row_g];
            float pg = pre[0][(128 + nn_g) * 2 + row_g] + pre[1][(128 + nn_g) * 2 + row_g];
            float po = pre[0][(192 + nn_g) * 2 + row_g] + pre[1][(192 + nn_g) * 2 + row_g];
            float iv = sigf(pi + xc0);
            float fv = sigf(pf + xc1);
            float gv = tanhfast(pg + xc2);
            float ov = sigf(po + xc3);
            c = fv * c + iv * gv;
            float hh = ov * tanhfast(c);
            hlast = hh;
            // launch the cross-CTA flight FIRST
            uint32_t pa = (t & 1) ? ph1 : ph0;
            asm volatile("st.shared::cluster.f32 [%0], %1;"
                         :: "r"(pa), "f"(hh) : "memory");
            hbuf[t & 1][row_g][n_g] = hh;
            __syncwarp();
            if ((tid & 31) == 0) {
                asm volatile("mbarrier.arrive.release.cluster.shared::cluster.b64 _, [%0];"
                             :: "r"(peer_bar) : "memory");
            }
            // off-path work after the send
            py[(size_t)t * HH] = hh;
            float xf0 = 0, xf1 = 0, xf2 = 0, xf3 = 0;
            if (t + 2 < TT) {
                const float* p2 = px + (size_t)(t + 2) * G4;
                xf0 = p2[0]; xf1 = p2[128]; xf2 = p2[256]; xf3 = p2[384];
            }
            xc0 = xn0; xc1 = xn1; xc2 = xn2; xc3 = xn3;
            xn0 = xf0; xn1 = xf1; xn2 = xf2; xn3 = xf3;
        }
        __syncthreads();
    }

    if (is_gate) {
        hNl[(b0 + row_g) * HH + n_g] = hlast;
        cNl[(b0 + row_g) * HH + n_g] = c;
    }
    asm volatile("barrier.cluster.arrive.aligned;" ::: "memory");
    asm volatile("barrier.cluster.wait.aligned;"   ::: "memory");
}

// ---------------------------------------------------------------------------
// Output projection: out[bt] = relu(y3[bt,:] . Wout + bout), one warp per row
// ---------------------------------------------------------------------------
__global__ __launch_bounds__(256)
void proj_kernel(const float* __restrict__ wout,
                 const float* __restrict__ bout,
                 float* __restrict__ out)
{
    int gwarp = (blockIdx.x * blockDim.x + threadIdx.x) >> 5;
    int lane  = threadIdx.x & 31;
    if (gwarp >= MROWS) return;
    float4 yv = ((const float4*)(g_y + (size_t)gwarp * HH))[lane];
    float4 wv = ((const float4*)wout)[lane];
    float s = yv.x * wv.x + yv.y * wv.y + yv.z * wv.z + yv.w * wv.w;
#pragma unroll
    for (int o = 16; o; o >>= 1) s += __shfl_xor_sync(0xFFFFFFFFu, s, o);
    if (lane == 0) out[gwarp] = fmaxf(s + bout[0], 0.f);
}

// ---------------------------------------------------------------------------
extern "C" void kernel_launch(void* const* d_in, const int* in_sizes, int n_in,
                              void* d_out, int out_size)
{
    const float* x    = (const float*)d_in[0];
    const float* h0   = (const float*)d_in[1];
    const float* c0   = (const float*)d_in[2];
    const float* Wih[3] = {(const float*)d_in[3], (const float*)d_in[7],  (const float*)d_in[11]};
    const float* Whh[3] = {(const float*)d_in[4], (const float*)d_in[8],  (const float*)d_in[12]};
    const float* bih[3] = {(const float*)d_in[5], (const float*)d_in[9],  (const float*)d_in[13]};
    const float* bhh[3] = {(const float*)d_in[6], (const float*)d_in[10], (const float*)d_in[14]};
    const float* Wout = (const float*)d_in[15];
    const float* bout = (const float*)d_in[16];

    float* out = (float*)d_out;           // [B*T]
    float* hN  = out + MROWS;             // [3,B,H]
    float* cN  = hN + 3 * BB * HH;        // [3,B,H]

    dim3 ggrid(G4 / 128, MROWS / 128);    // (4, 1024)

    xg_gemm<64><<<ggrid, 256>>>(x, 0, Wih[0], bih[0], bhh[0]);
    lstm_rec3<<<BB, 512>>>(Whh[0], h0, c0, hN, cN);

    xg_gemm<128><<<ggrid, 256>>>(nullptr, 1, Wih[1], bih[1], bhh[1]);
    lstm_rec3<<<BB, 512>>>(Whh[1], h0 + BB * HH, c0 + BB * HH,
                           hN + BB * HH, cN + BB * HH);

    xg_gemm<128><<<ggrid, 256>>>(nullptr, 1, Wih[2], bih[2], bhh[2]);
    lstm_rec3<<<BB, 512>>>(Whh[2], h0 + 2 * BB * HH, c0 + 2 * BB * HH,
                           hN + 2 * BB * HH, cN + 2 * BB * HH);

    proj_kernel<<<MROWS / 8, 256>>>(Wout, bout, out);
}

// round 5
// speedup vs baseline: 1.0250x; 1.0250x over previous
#include <cuda_runtime.h>
#include <cstdint>

typedef unsigned long long ULL;

// Problem constants: B=128, T=1024, H=128, D=64, L=3
#define BB   128
#define TT   1024
#define HH   128
#define G4   512
#define MROWS (BB*TT)

// Scratch (device globals: allocation-rule-safe)
__device__ float g_xg[(size_t)MROWS * G4];   // 256 MB
__device__ float g_y [(size_t)MROWS * HH];   // 64 MB

// ---------------------------------------------------------------------------
// helpers
// ---------------------------------------------------------------------------
__device__ __forceinline__ void fma2(ULL& acc, ULL a, ULL b) {
    asm("fma.rn.f32x2 %0, %1, %2, %0;" : "+l"(acc) : "l"(a), "l"(b));
}
__device__ __forceinline__ ULL pk2(float lo, float hi) {
    ULL r; asm("mov.b64 %0, {%1, %2};" : "=l"(r) : "f"(lo), "f"(hi)); return r;
}
__device__ __forceinline__ void upk2(ULL v, float& lo, float& hi) {
    asm("mov.b64 {%0, %1}, %2;" : "=f"(lo), "=f"(hi) : "l"(v));
}
__device__ __forceinline__ float tanhapx(float x) {
    float y; asm("tanh.approx.f32 %0, %1;" : "=f"(y) : "f"(x)); return y;
}
__device__ __forceinline__ float sigapx(float x) {        // 1-MUFU sigmoid
    return fmaf(tanhapx(0.5f * x), 0.5f, 0.5f);
}
__device__ __forceinline__ uint32_t smem_u32(const void* p) {
    uint32_t a;
    asm("{ .reg .u64 t; cvta.to.shared.u64 t, %1; cvt.u32.u64 %0, t; }"
        : "=r"(a) : "l"(p));
    return a;
}
__device__ __forceinline__ uint32_t mapa_u32(uint32_t a, uint32_t rank) {
    uint32_t r;
    asm("mapa.shared::cluster.u32 %0, %1, %2;" : "=r"(r) : "r"(a), "r"(rank));
    return r;
}

// ---------------------------------------------------------------------------
// xg GEMM: g_xg[m, 0:512] = A[m, 0:K] @ W[512, K]^T + (bih + bhh)
// BM=BN=128, BK=8, 256 threads, 8x8 tile, f32x2; smem ping-pong (1 sync/chunk)
// ---------------------------------------------------------------------------
template<int K>
__global__ __launch_bounds__(256, 2)
void xg_gemm(const float* __restrict__ Aext, int use_gy,
             const float* __restrict__ W,
             const float* __restrict__ bih,
             const float* __restrict__ bhh)
{
    const int BM = 128, BN = 128, BK = 8;
    __shared__ __align__(16) float As[2][BK][BM + 4];
    __shared__ __align__(16) float Bs[2][BK][BN + 4];

    const float* A = use_gy ? (const float*)g_y : Aext;
    float* out = g_xg;

    int tid = threadIdx.x;
    int tx = tid & 15, ty = tid >> 4;
    int m0 = blockIdx.y * BM, n0 = blockIdx.x * BN;

    int am = tid >> 1, ak = (tid & 1) * 4;
    int wn = tid >> 1, wk = (tid & 1) * 4;

    ULL acc[8][4];
#pragma unroll
    for (int i = 0; i < 8; i++)
#pragma unroll
        for (int j = 0; j < 4; j++) acc[i][j] = 0ULL;

    // chunk 0 -> buf 0
    float4 a_ld = *(const float4*)(A + (size_t)(m0 + am) * K + ak);
    float4 b_ld = *(const float4*)(W + (size_t)(n0 + wn) * K + wk);
    As[0][ak + 0][am] = a_ld.x; As[0][ak + 1][am] = a_ld.y;
    As[0][ak + 2][am] = a_ld.z; As[0][ak + 3][am] = a_ld.w;
    Bs[0][wk + 0][wn] = b_ld.x; Bs[0][wk + 1][wn] = b_ld.y;
    Bs[0][wk + 2][wn] = b_ld.z; Bs[0][wk + 3][wn] = b_ld.w;
    __syncthreads();

    const int NC = K / BK;
#pragma unroll 2
    for (int c = 0; c < NC; ++c) {
        int cur = c & 1, nxt = cur ^ 1;
        if (c + 1 < NC) {
            a_ld = *(const float4*)(A + (size_t)(m0 + am) * K + (c + 1) * BK + ak);
            b_ld = *(const float4*)(W + (size_t)(n0 + wn) * K + (c + 1) * BK + wk);
        }

#pragma unroll
        for (int k = 0; k < BK; k++) {
            float4 t0 = *(const float4*)&As[cur][k][ty * 8];
            float4 t1 = *(const float4*)&As[cur][k][ty * 8 + 4];
            float av[8] = {t0.x, t0.y, t0.z, t0.w, t1.x, t1.y, t1.z, t1.w};
            const ulonglong2* bbp = (const ulonglong2*)(&Bs[cur][k][tx * 8]);
            ulonglong2 b01 = bbp[0];
            ulonglong2 b23 = bbp[1];
#pragma unroll
            for (int i = 0; i < 8; i++) {
                ULL ai = pk2(av[i], av[i]);
                fma2(acc[i][0], ai, b01.x);
                fma2(acc[i][1], ai, b01.y);
                fma2(acc[i][2], ai, b23.x);
                fma2(acc[i][3], ai, b23.y);
            }
        }

        if (c + 1 < NC) {
            As[nxt][ak + 0][am] = a_ld.x; As[nxt][ak + 1][am] = a_ld.y;
            As[nxt][ak + 2][am] = a_ld.z; As[nxt][ak + 3][am] = a_ld.w;
            Bs[nxt][wk + 0][wn] = b_ld.x; Bs[nxt][wk + 1][wn] = b_ld.y;
            Bs[nxt][wk + 2][wn] = b_ld.z; Bs[nxt][wk + 3][wn] = b_ld.w;
            __syncthreads();
        }
    }

    float bias[8];
#pragma unroll
    for (int j = 0; j < 8; j++) {
        int n = n0 + tx * 8 + j;
        bias[j] = bih[n] + bhh[n];
    }
#pragma unroll
    for (int i = 0; i < 8; i++) {
        size_t row = (size_t)(m0 + ty * 8 + i) * G4 + n0 + tx * 8;
#pragma unroll
        for (int j = 0; j < 4; j++) {
            float lo, hi; upk2(acc[i][j], lo, hi);
            float2 v = make_float2(lo + bias[2 * j], hi + bias[2 * j + 1]);
            *(float2*)(out + row + 2 * j) = v;
        }
    }
}

// ---------------------------------------------------------------------------
// Recurrent scan — R3's PROVEN sync skeleton (mid + end __syncthreads, mbar
// count=4 w/ lane-0 arrives), with:
//   * tanh.approx nonlinearities (1 MUFU each)
//   * y-store + xg prefetch moved AFTER the end-of-step sync (off critical path)
// Cluster of 2 CTAs / 2 batch rows; rank r owns h-cols [r*64, r*64+64).
// ---------------------------------------------------------------------------
__global__ __launch_bounds__(512, 1) __cluster_dims__(2, 1, 1)
void lstm_rec5(const float* __restrict__ whh,
               const float* __restrict__ h0l,
               const float* __restrict__ c0l,
               float* __restrict__ hNl,
               float* __restrict__ cNl)
{
    __shared__ __align__(16) float hbuf[2][2][132];  // [parity][row][n] padded
    __shared__ __align__(8)  float pre[2][512];      // [kh][jp*2 + row]
    __shared__ __align__(8)  ULL   bar;

    const int tid = threadIdx.x;
    const int r   = blockIdx.x & 1;
    const int b0  = (blockIdx.x >> 1) * 2;

    const int kh = tid >> 8;
    const int jp = tid & 255;
    const int g  = jp >> 6;
    const int nn = jp & 63;

    uint32_t bar_addr = smem_u32(&bar);
    uint32_t peer_bar = mapa_u32(bar_addr, (uint32_t)(r ^ 1));

    if (tid == 0) {
        asm volatile("mbarrier.init.shared.b64 [%0], %1;"
                     :: "r"(bar_addr), "r"(4) : "memory");
    }
    if (tid < 256) {
        int row = tid >> 7, n = tid & 127;
        hbuf[1][row][n] = h0l[(b0 + row) * HH + n];
    }

    const int row_w = g * 128 + r * 64 + nn;
    ULL w2[32];
    const ULL* wp = (const ULL*)(whh + row_w * HH + kh * 64);
#pragma unroll
    for (int i = 0; i < 32; i++) w2[i] = wp[i];

    // gate role: first 128 threads of the PEER-k warp group
    const bool is_gate = (kh == (r ^ 1)) && (jp < 128);
    const int row_g = jp & 1;
    const int nn_g  = jp >> 1;
    const int n_g   = r * 64 + nn_g;

    float c = 0.f, hlast = 0.f;
    const float* px = g_xg + ((size_t)(b0 + row_g) * TT) * G4 + n_g;
    float*       py = g_y  + ((size_t)(b0 + row_g) * TT) * HH + n_g;
    uint32_t ph0 = 0, ph1 = 0;
    float xc0=0,xc1=0,xc2=0,xc3=0, xn0=0,xn1=0,xn2=0,xn3=0;
    if (is_gate) {
        c   = c0l[(b0 + row_g) * HH + n_g];
        ph0 = mapa_u32(smem_u32(&hbuf[0][row_g][n_g]), (uint32_t)(r ^ 1));
        ph1 = mapa_u32(smem_u32(&hbuf[1][row_g][n_g]), (uint32_t)(r ^ 1));
        xc0 = px[0];        xc1 = px[128];        xc2 = px[256];        xc3 = px[384];
        xn0 = px[G4 + 0];   xn1 = px[G4 + 128];   xn2 = px[G4 + 256];   xn3 = px[G4 + 384];
    }

    __syncthreads();
    asm volatile("barrier.cluster.arrive.aligned;" ::: "memory");
    asm volatile("barrier.cluster.wait.aligned;"   ::: "memory");

    for (int t = 0; t < TT; ++t) {
        const int pr = (t + 1) & 1;              // parity holding h(t-1)

        if (kh != r && t > 0) {                  // peer-k warps wait for h(t-1)
            unsigned par = (unsigned)((t - 1) & 1);
            asm volatile(
                "{\n\t"
                ".reg .pred P1;\n\t"
                "WLP%=:\n\t"
                "mbarrier.try_wait.parity.acquire.cluster.shared::cta.b64 P1, [%0], %1, 0x989680;\n\t"
                "@!P1 bra WLP%=;\n\t"
                "}"
                :: "r"(bar_addr), "r"(par) : "memory");
        }

        // matvec over this thread's 64-k half, both batch rows
        ULL a00 = 0, a01 = 0, a10 = 0, a11 = 0;
        const ulonglong2* hv0 = (const ulonglong2*)&hbuf[pr][0][kh * 64];
        const ulonglong2* hv1 = (const ulonglong2*)&hbuf[pr][1][kh * 64];
#pragma unroll
        for (int i = 0; i < 16; i++) {
            ulonglong2 u0 = hv0[i], u1 = hv1[i];
            fma2(a00, w2[2 * i],     u0.x);
            fma2(a01, w2[2 * i + 1], u0.y);
            fma2(a10, w2[2 * i],     u1.x);
            fma2(a11, w2[2 * i + 1], u1.y);
        }
        float s0, s1;
        { float x0,x1,x2,x3; upk2(a00,x0,x1); upk2(a01,x2,x3); s0 = (x0+x1)+(x2+x3); }
        { float x0,x1,x2,x3; upk2(a10,x0,x1); upk2(a11,x2,x3); s1 = (x0+x1)+(x2+x3); }
        *(float2*)&pre[kh][jp * 2] = make_float2(s0, s1);
        __syncthreads();                         // pre[] ready

        if (is_gate) {
            float pi = pre[0][(      nn_g) * 2 + row_g] + pre[1][(      nn_g) * 2 + row_g];
            float pf = pre[0][( 64 + nn_g) * 2 + row_g] + pre[1][( 64 + nn_g) * 2 + row_g];
            float pg = pre[0][(128 + nn_g) * 2 + row_g] + pre[1][(128 + nn_g) * 2 + row_g];
            float po = pre[0][(192 + nn_g) * 2 + row_g] + pre[1][(192 + nn_g) * 2 + row_g];
            float iv = sigapx(pi + xc0);
            float fv = sigapx(pf + xc1);
            float gv = tanhapx(pg + xc2);
            float ov = sigapx(po + xc3);
            c = fv * c + iv * gv;
            float hh = ov * tanhapx(c);
            hlast = hh;
            // cross-CTA flight first
            uint32_t pa = (t & 1) ? ph1 : ph0;
            asm volatile("st.shared::cluster.f32 [%0], %1;"
                         :: "r"(pa), "f"(hh) : "memory");
            hbuf[t & 1][row_g][n_g] = hh;
            __syncwarp();
            if ((tid & 31) == 0) {
                asm volatile("mbarrier.arrive.release.cluster.shared::cluster.b64 _, [%0];"
                             :: "r"(peer_bar) : "memory");
            }
        }
        __syncthreads();                         // hbuf local half ready

        // off the critical path: everyone else is already in next matvec wait
        if (is_gate) {
            py[(size_t)t * HH] = hlast;
            float xf0 = 0, xf1 = 0, xf2 = 0, xf3 = 0;
            if (t + 2 < TT) {
                const float* p2 = px + (size_t)(t + 2) * G4;
                xf0 = p2[0]; xf1 = p2[128]; xf2 = p2[256]; xf3 = p2[384];
            }
            xc0 = xn0; xc1 = xn1; xc2 = xn2; xc3 = xn3;
            xn0 = xf0; xn1 = xf1; xn2 = xf2; xn3 = xf3;
        }
    }

    if (is_gate) {
        hNl[(b0 + row_g) * HH + n_g] = hlast;
        cNl[(b0 + row_g) * HH + n_g] = c;
    }
    asm volatile("barrier.cluster.arrive.aligned;" ::: "memory");
    asm volatile("barrier.cluster.wait.aligned;"   ::: "memory");
}

// ---------------------------------------------------------------------------
// Output projection: out[bt] = relu(y3[bt,:] . Wout + bout), one warp per row
// ---------------------------------------------------------------------------
__global__ __launch_bounds__(256)
void proj_kernel(const float* __restrict__ wout,
                 const float* __restrict__ bout,
                 float* __restrict__ out)
{
    int gwarp = (blockIdx.x * blockDim.x + threadIdx.x) >> 5;
    int lane  = threadIdx.x & 31;
    if (gwarp >= MROWS) return;
    float4 yv = ((const float4*)(g_y + (size_t)gwarp * HH))[lane];
    float4 wv = ((const float4*)wout)[lane];
    float s = yv.x * wv.x + yv.y * wv.y + yv.z * wv.z + yv.w * wv.w;
#pragma unroll
    for (int o = 16; o; o >>= 1) s += __shfl_xor_sync(0xFFFFFFFFu, s, o);
    if (lane == 0) out[gwarp] = fmaxf(s + bout[0], 0.f);
}

// ---------------------------------------------------------------------------
extern "C" void kernel_launch(void* const* d_in, const int* in_sizes, int n_in,
                              void* d_out, int out_size)
{
    const float* x    = (const float*)d_in[0];
    const float* h0   = (const float*)d_in[1];
    const float* c0   = (const float*)d_in[2];
    const float* Wih[3] = {(const float*)d_in[3], (const float*)d_in[7],  (const float*)d_in[11]};
    const float* Whh[3] = {(const float*)d_in[4], (const float*)d_in[8],  (const float*)d_in[12]};
    const float* bih[3] = {(const float*)d_in[5], (const float*)d_in[9],  (const float*)d_in[13]};
    const float* bhh[3] = {(const float*)d_in[6], (const float*)d_in[10], (const float*)d_in[14]};
    const float* Wout = (const float*)d_in[15];
    const float* bout = (const float*)d_in[16];

    float* out = (float*)d_out;           // [B*T]
    float* hN  = out + MROWS;             // [3,B,H]
    float* cN  = hN + 3 * BB * HH;        // [3,B,H]

    dim3 ggrid(G4 / 128, MROWS / 128);    // (4, 1024)

    xg_gemm<64><<<ggrid, 256>>>(x, 0, Wih[0], bih[0], bhh[0]);
    lstm_rec5<<<BB, 512>>>(Whh[0], h0, c0, hN, cN);

    xg_gemm<128><<<ggrid, 256>>>(nullptr, 1, Wih[1], bih[1], bhh[1]);
    lstm_rec5<<<BB, 512>>>(Whh[1], h0 + BB * HH, c0 + BB * HH,
                           hN + BB * HH, cN + BB * HH);

    xg_gemm<128><<<ggrid, 256>>>(nullptr, 1, Wih[2], bih[2], bhh[2]);
    lstm_rec5<<<BB, 512>>>(Whh[2], h0 + 2 * BB * HH, c0 + 2 * BB * HH,
                           hN + 2 * BB * HH, cN + 2 * BB * HH);

    proj_kernel<<<MROWS / 8, 256>>>(Wout, bout, out);
}